// round 9
// baseline (speedup 1.0000x reference)
#include <cuda_runtime.h>

// GEMV: y = alpha * (A @ x) + beta * b
// A: [16384,16384] f32. RPB=4 at forced 32 regs: 17% fewer LDG instructions
// per A-byte than RPB=2 (5 LDG / 64B vs 3 LDG / 32B), x L1 traffic /2.
// Body consumes each A-float4 immediately -> ~24 live regs, no spill,
// occ stays ~95% under launch_bounds(256,8).

#define ROWS 16384
#define COLS 16384
#define TPB  256
#define RPB  4

__global__ __launch_bounds__(TPB, 8) void gemv_kernel(
    const float* __restrict__ alpha,
    const float* __restrict__ A,
    const float* __restrict__ x,
    const float* __restrict__ beta,
    const float* __restrict__ b,
    float* __restrict__ y)
{
    const int row0 = blockIdx.x * RPB;
    const int tid  = threadIdx.x;

    const float4* __restrict__ r0 = reinterpret_cast<const float4*>(A + (size_t)(row0 + 0) * COLS);
    const float4* __restrict__ r1 = reinterpret_cast<const float4*>(A + (size_t)(row0 + 1) * COLS);
    const float4* __restrict__ r2 = reinterpret_cast<const float4*>(A + (size_t)(row0 + 2) * COLS);
    const float4* __restrict__ r3 = reinterpret_cast<const float4*>(A + (size_t)(row0 + 3) * COLS);
    const float4* __restrict__ xv = reinterpret_cast<const float4*>(x);

    float acc0 = 0.0f, acc1 = 0.0f, acc2 = 0.0f, acc3 = 0.0f;

    // COLS/4 = 4096 float4; 256 threads -> 16 iterations each.
    #pragma unroll 2
    for (int i = tid; i < COLS / 4; i += TPB) {
        float4 v = __ldg(&xv[i]);
        // consume each A vector immediately: <=1 live A temp
        {
            float4 a = __ldcs(&r0[i]);
            acc0 = fmaf(a.x, v.x, acc0); acc0 = fmaf(a.y, v.y, acc0);
            acc0 = fmaf(a.z, v.z, acc0); acc0 = fmaf(a.w, v.w, acc0);
        }
        {
            float4 a = __ldcs(&r1[i]);
            acc1 = fmaf(a.x, v.x, acc1); acc1 = fmaf(a.y, v.y, acc1);
            acc1 = fmaf(a.z, v.z, acc1); acc1 = fmaf(a.w, v.w, acc1);
        }
        {
            float4 a = __ldcs(&r2[i]);
            acc2 = fmaf(a.x, v.x, acc2); acc2 = fmaf(a.y, v.y, acc2);
            acc2 = fmaf(a.z, v.z, acc2); acc2 = fmaf(a.w, v.w, acc2);
        }
        {
            float4 a = __ldcs(&r3[i]);
            acc3 = fmaf(a.x, v.x, acc3); acc3 = fmaf(a.y, v.y, acc3);
            acc3 = fmaf(a.z, v.z, acc3); acc3 = fmaf(a.w, v.w, acc3);
        }
    }

    // warp reduce all accumulators
    #pragma unroll
    for (int off = 16; off > 0; off >>= 1) {
        acc0 += __shfl_xor_sync(0xFFFFFFFFu, acc0, off);
        acc1 += __shfl_xor_sync(0xFFFFFFFFu, acc1, off);
        acc2 += __shfl_xor_sync(0xFFFFFFFFu, acc2, off);
        acc3 += __shfl_xor_sync(0xFFFFFFFFu, acc3, off);
    }

    __shared__ float warp_sums[RPB][TPB / 32];
    const int lane = tid & 31;
    const int wid  = tid >> 5;
    if (lane == 0) {
        warp_sums[0][wid] = acc0;
        warp_sums[1][wid] = acc1;
        warp_sums[2][wid] = acc2;
        warp_sums[3][wid] = acc3;
    }
    __syncthreads();

    // warp 0: lanes 0..31 cover 4 rows x 8 warp-sums
    if (wid == 0) {
        const int r = lane >> 3;
        const int w = lane & 7;
        float s = warp_sums[r][w];
        #pragma unroll
        for (int off = 4; off > 0; off >>= 1)
            s += __shfl_xor_sync(0xFFFFFFFFu, s, off);
        if (w == 0)
            y[row0 + r] = alpha[0] * s + beta[0] * b[row0 + r];
    }
}

extern "C" void kernel_launch(void* const* d_in, const int* in_sizes, int n_in,
                              void* d_out, int out_size) {
    const float* alpha = (const float*)d_in[0];
    const float* A     = (const float*)d_in[1];
    const float* x     = (const float*)d_in[2];
    const float* beta  = (const float*)d_in[3];
    const float* b     = (const float*)d_in[4];
    float* y = (float*)d_out;

    gemv_kernel<<<ROWS / RPB, TPB>>>(alpha, A, x, beta, b, y);
}

// round 10
// speedup vs baseline: 1.0542x; 1.0542x over previous
#include <cuda_runtime.h>

// GEMV: y = alpha * (A @ x) + beta * b
// A: [16384,16384] f32. RPB=1 at forced 8 CTAs/SM: each CTA streams ONE
// contiguous 64KB row -> fewest concurrent DRAM streams, best row-buffer
// locality. unroll 4 front-batches 4 independent LDG.128 per thread.

#define ROWS 16384
#define COLS 16384
#define TPB  256

__global__ __launch_bounds__(TPB, 8) void gemv_kernel(
    const float* __restrict__ alpha,
    const float* __restrict__ A,
    const float* __restrict__ x,
    const float* __restrict__ beta,
    const float* __restrict__ b,
    float* __restrict__ y)
{
    const int row = blockIdx.x;
    const int tid = threadIdx.x;

    const float4* __restrict__ arow = reinterpret_cast<const float4*>(A + (size_t)row * COLS);
    const float4* __restrict__ xv   = reinterpret_cast<const float4*>(x);

    float acc = 0.0f;

    // COLS/4 = 4096 float4; 256 threads -> 16 iterations; unroll 4.
    #pragma unroll 4
    for (int i = tid; i < COLS / 4; i += TPB) {
        float4 a = __ldcs(&arow[i]);
        float4 v = __ldg(&xv[i]);
        acc = fmaf(a.x, v.x, acc);
        acc = fmaf(a.y, v.y, acc);
        acc = fmaf(a.z, v.z, acc);
        acc = fmaf(a.w, v.w, acc);
    }

    // warp reduce
    #pragma unroll
    for (int off = 16; off > 0; off >>= 1)
        acc += __shfl_xor_sync(0xFFFFFFFFu, acc, off);

    __shared__ float warp_sums[TPB / 32];
    const int lane = tid & 31;
    const int wid  = tid >> 5;
    if (lane == 0) warp_sums[wid] = acc;
    __syncthreads();

    if (wid == 0) {
        float s = (lane < TPB / 32) ? warp_sums[lane] : 0.0f;
        #pragma unroll
        for (int off = 4; off > 0; off >>= 1)
            s += __shfl_xor_sync(0xFFFFFFFFu, s, off);
        if (lane == 0)
            y[row] = alpha[0] * s + beta[0] * b[row];
    }
}

extern "C" void kernel_launch(void* const* d_in, const int* in_sizes, int n_in,
                              void* d_out, int out_size) {
    const float* alpha = (const float*)d_in[0];
    const float* A     = (const float*)d_in[1];
    const float* x     = (const float*)d_in[2];
    const float* beta  = (const float*)d_in[3];
    const float* b     = (const float*)d_in[4];
    float* y = (float*)d_out;

    gemv_kernel<<<ROWS, TPB>>>(alpha, A, x, beta, b, y);
}